// round 11
// baseline (speedup 1.0000x reference)
#include <cuda_runtime.h>
#include <cstdint>

// ----------------------------------------------------------------------------
// WindowAttention: 2048 windows x 8 heads, M=N=64, D=64, fp32.
// PERSISTENT kernel: 296 CTAs (2/SM), 128 threads / 4 warps, each CTA loops
// over ~55 (b,h) windows with DOUBLE-BUFFERED cp.async prefetch of the next
// window's Q,K,V during the current window's compute -> continuous DRAM stream.
// Warp w owns query rows [16w,16w+16). QK: Q exact tf32 hi+lo, K raw fp32 as
// tf32. PV: P exact hi+lo, V raw. P reuses K region, O reuses Q region.
// Bias pre-laid-out in fragment order (L2-resident). Rolled coalesced stores.
// ----------------------------------------------------------------------------

#define GRIDN 296
#define NWIN  16384
#define QSTR 68                       // mod 32 == 4 -> conflict-free frags
#define KSTR 68
#define VSTR 72                       // mod 32 == 8 -> conflict-free V frags
#define QOFF 0
#define KOFF 4352                     // 64*68
#define VOFF 8704                     // 2*64*68
#define BUF_FLOATS 13312              // 8704 + 64*72
#define SCALE_L2E 0.1803368801111146f // 0.125 * log2(e)

// bias fragment order: [h][warp][n][lane] float4 =
//  { b[rA][8n+2tig], b[rA][8n+2tig+1], b[rA+8][8n+2tig], b[rA+8][8n+2tig+1] } * log2e
// rA = 16*warp + (lane>>2).  8*4*8*32 float4 = 128 KB, L2-resident.
__device__ float4 g_biasF[8 * 4 * 8 * 32];

__global__ void bias_precompute_kernel(const float* __restrict__ table) {
    int t = blockIdx.x * blockDim.x + threadIdx.x;   // 0..8191
    if (t >= 8192) return;
    int h = t >> 10, blk = (t >> 8) & 3, n = (t >> 5) & 7, lane = t & 31;
    int g = lane >> 2, tig = lane & 3;
    int rA = 16 * blk + g, rB = rA + 8;
    int col = 8 * n + 2 * tig;
    const float L2E = 1.4426950408889634f;
    float4 r;
#define BIAS_AT(rr, cc, dst) {                                   \
        int raw = ((rr) - 32) * 128 + ((cc) - 32) + 64;          \
        int idx = raw < 0 ? raw + 16129 : raw;                   \
        dst = table[(size_t)idx * 8 + h] * L2E; }
    BIAS_AT(rA, col,     r.x);
    BIAS_AT(rA, col + 1, r.y);
    BIAS_AT(rB, col,     r.z);
    BIAS_AT(rB, col + 1, r.w);
#undef BIAS_AT
    g_biasF[t] = r;
}

__device__ __forceinline__ uint32_t f2tf32(float x) {
    uint32_t r;
    asm("cvt.rna.tf32.f32 %0, %1;" : "=r"(r) : "f"(x));
    return r;
}

__device__ __forceinline__ void split_tf32(float x, uint32_t& hi, uint32_t& lo) {
    hi = f2tf32(x);
    lo = f2tf32(x - __uint_as_float(hi));
}

__device__ __forceinline__ void mma_tf32(float c[4],
                                         uint32_t a0, uint32_t a1, uint32_t a2, uint32_t a3,
                                         uint32_t b0, uint32_t b1) {
    asm volatile(
        "mma.sync.aligned.m16n8k8.row.col.f32.tf32.tf32.f32 "
        "{%0,%1,%2,%3}, {%4,%5,%6,%7}, {%8,%9}, {%0,%1,%2,%3};"
        : "+f"(c[0]), "+f"(c[1]), "+f"(c[2]), "+f"(c[3])
        : "r"(a0), "r"(a1), "r"(a2), "r"(a3), "r"(b0), "r"(b1));
}

__device__ __forceinline__ void cp16(uint32_t smem_dst, const void* gmem_src) {
    asm volatile("cp.async.cg.shared.global [%0], [%1], 16;"
                 :: "r"(smem_dst), "l"(gmem_src));
}

// prefetch one window's Q,K,V into buffer at smem byte offset bufu (128 thr)
__device__ __forceinline__ void prefetch_win(uint32_t bufu,
                                             const float* __restrict__ q,
                                             const float* __restrict__ k,
                                             const float* __restrict__ v,
                                             int wi, int tid) {
    const float4* qg = (const float4*)(q + (size_t)wi * 4096);
    const float4* kg = (const float4*)(k + (size_t)wi * 4096);
    const float4* vg = (const float4*)(v + (size_t)wi * 4096);
#pragma unroll
    for (int j = 0; j < 8; ++j) {
        int i = tid + 128 * j;
        int m = i >> 4, c4 = i & 15;
        cp16(bufu + (QOFF + m * QSTR + c4 * 4) * 4, qg + i);
        cp16(bufu + (KOFF + m * KSTR + c4 * 4) * 4, kg + i);
        cp16(bufu + (VOFF + m * VSTR + c4 * 4) * 4, vg + i);
    }
}

__global__ __launch_bounds__(128, 2) void winattn_kernel(
    const float* __restrict__ q, const float* __restrict__ k,
    const float* __restrict__ v, float* __restrict__ out) {
    extern __shared__ float smem[];

    const int tid  = threadIdx.x;
    const int lane = tid & 31;
    const int g    = lane >> 2;          // 0..7
    const int tig  = lane & 3;           // 0..3
    const int w    = tid >> 5;           // warp 0..3
    const int r0   = w * 16;             // warp's first query row

    const int cta = blockIdx.x;
    const int cnt = (NWIN - cta + GRIDN - 1) / GRIDN;
    const uint32_t smu = (uint32_t)__cvta_generic_to_shared(smem);

    // prime the pipeline: window 0 of this CTA into buffer 0
    prefetch_win(smu, q, k, v, cta, tid);
    asm volatile("cp.async.commit_group;");

    for (int it = 0; it < cnt; ++it) {
        const int wi  = cta + it * GRIDN;
        const int cur = it & 1;

        // issue next window's prefetch into the other buffer, then one group
        if (it + 1 < cnt)
            prefetch_win(smu + ((it + 1) & 1) * (BUF_FLOATS * 4), q, k, v,
                         wi + GRIDN, tid);
        asm volatile("cp.async.commit_group;");
        // allow the newest group to pend; window-i's group is complete
        asm volatile("cp.async.wait_group 1;" ::: "memory");
        __syncthreads();

        float* bQ = smem + cur * BUF_FLOATS;
        float* bK = bQ + KOFF;
        float* bV = bQ + VOFF;
        const int b = wi >> 3, h = wi & 7;

        // ---- S = Q K^T : Q exact (hi+lo), K raw fp32 as tf32 ----------------
        float c[8][4];
#pragma unroll
        for (int n = 0; n < 8; ++n) {
#pragma unroll
            for (int j = 0; j < 4; ++j) c[n][j] = 0.f;
        }

#pragma unroll
        for (int ks = 0; ks < 8; ++ks) {
            const int kc = ks * 8 + tig;
            uint32_t h0, l0, h1, l1, h2, l2, h3, l3;
            split_tf32(bQ[(r0 + g) * QSTR + kc],         h0, l0);
            split_tf32(bQ[(r0 + g + 8) * QSTR + kc],     h1, l1);
            split_tf32(bQ[(r0 + g) * QSTR + kc + 4],     h2, l2);
            split_tf32(bQ[(r0 + g + 8) * QSTR + kc + 4], h3, l3);
#pragma unroll
            for (int n = 0; n < 8; ++n) {
                uint32_t b0 = __float_as_uint(bK[(n * 8 + g) * KSTR + kc]);
                uint32_t b1 = __float_as_uint(bK[(n * 8 + g) * KSTR + kc + 4]);
                mma_tf32(c[n], h0, h1, h2, h3, b0, b1);
                mma_tf32(c[n], l0, l1, l2, l3, b0, b1);
            }
        }

        // ---- scale + bias (fragment order, coalesced, L2-resident) ----------
        {
            const float4* bf = g_biasF + ((h * 4 + w) * 8) * 32 + lane;
#pragma unroll
            for (int n = 0; n < 8; ++n) {
                float4 bb = bf[n * 32];
                c[n][0] = fmaf(c[n][0], SCALE_L2E, bb.x);
                c[n][1] = fmaf(c[n][1], SCALE_L2E, bb.y);
                c[n][2] = fmaf(c[n][2], SCALE_L2E, bb.z);
                c[n][3] = fmaf(c[n][3], SCALE_L2E, bb.w);
            }
        }

        // ---- softmax (base-2 domain; quad holds a full row) -----------------
        float mx0 = -1e30f, mx1 = -1e30f;
#pragma unroll
        for (int n = 0; n < 8; ++n) {
            mx0 = fmaxf(mx0, fmaxf(c[n][0], c[n][1]));
            mx1 = fmaxf(mx1, fmaxf(c[n][2], c[n][3]));
        }
#pragma unroll
        for (int d = 1; d <= 2; d <<= 1) {
            mx0 = fmaxf(mx0, __shfl_xor_sync(0xffffffffu, mx0, d));
            mx1 = fmaxf(mx1, __shfl_xor_sync(0xffffffffu, mx1, d));
        }
        float s0 = 0.f, s1 = 0.f;
#pragma unroll
        for (int n = 0; n < 8; ++n) {
            c[n][0] = exp2f(c[n][0] - mx0);
            c[n][1] = exp2f(c[n][1] - mx0);
            c[n][2] = exp2f(c[n][2] - mx1);
            c[n][3] = exp2f(c[n][3] - mx1);
            s0 += c[n][0] + c[n][1];
            s1 += c[n][2] + c[n][3];
        }
#pragma unroll
        for (int d = 1; d <= 2; d <<= 1) {
            s0 += __shfl_xor_sync(0xffffffffu, s0, d);
            s1 += __shfl_xor_sync(0xffffffffu, s1, d);
        }
        float inv0 = 1.0f / s0, inv1 = 1.0f / s1;

        // ---- all warps past QK: K and Q regions reusable ---------------------
        __syncthreads();

        // ---- stage unnormalized P over K region (warp-private rows) ---------
#pragma unroll
        for (int n = 0; n < 8; ++n) {
            int col = n * 8 + 2 * tig;
            *(float2*)(bK + (r0 + g) * KSTR + col)     = make_float2(c[n][0], c[n][1]);
            *(float2*)(bK + (r0 + g + 8) * KSTR + col) = make_float2(c[n][2], c[n][3]);
        }
        __syncwarp();

        // ---- O = P V : P exact (hi+lo), V raw fp32 as tf32 -------------------
        float o[8][4];
#pragma unroll
        for (int d = 0; d < 8; ++d) {
#pragma unroll
            for (int j = 0; j < 4; ++j) o[d][j] = 0.f;
        }

#pragma unroll
        for (int ks = 0; ks < 8; ++ks) {
            const int kc = ks * 8 + tig;
            uint32_t h0, l0, h1, l1, h2, l2, h3, l3;
            split_tf32(bK[(r0 + g) * KSTR + kc],         h0, l0);
            split_tf32(bK[(r0 + g + 8) * KSTR + kc],     h1, l1);
            split_tf32(bK[(r0 + g) * KSTR + kc + 4],     h2, l2);
            split_tf32(bK[(r0 + g + 8) * KSTR + kc + 4], h3, l3);
#pragma unroll
            for (int dt = 0; dt < 8; ++dt) {
                uint32_t b0 = __float_as_uint(bV[(ks * 8 + tig) * VSTR + dt * 8 + g]);
                uint32_t b1 = __float_as_uint(bV[(ks * 8 + tig + 4) * VSTR + dt * 8 + g]);
                mma_tf32(o[dt], h0, h1, h2, h3, b0, b1);
                mma_tf32(o[dt], l0, l1, l2, l3, b0, b1);
            }
        }

        // ---- stage normalized O over Q region (warp-private rows) -----------
#pragma unroll
        for (int dt = 0; dt < 8; ++dt) {
            int col = dt * 8 + 2 * tig;
            *(float2*)(bQ + (r0 + g) * QSTR + col)     = make_float2(o[dt][0] * inv0, o[dt][1] * inv0);
            *(float2*)(bQ + (r0 + g + 8) * QSTR + col) = make_float2(o[dt][2] * inv1, o[dt][3] * inv1);
        }
        __syncthreads();

        // out[b*32768 + row*512 + ((h*64 + d - 32) & 511)], row-major float4
        {
            float* ob = out + (size_t)b * 32768;
            const int cbase = h * 64 - 32;
            const int c4 = tid & 15;            // 16 float4 per row
            const int col = (cbase + 4 * c4) & 511;
#pragma unroll
            for (int it2 = 0; it2 < 8; ++it2) {
                int row = (tid >> 4) + 8 * it2;
                float4 val = *(const float4*)(bQ + row * QSTR + c4 * 4);
                *(float4*)(ob + row * 512 + col) = val;
            }
        }
        // stores done before next iteration's prefetch overwrites this buffer
        __syncthreads();
    }
}

extern "C" void kernel_launch(void* const* d_in, const int* in_sizes, int n_in,
                              void* d_out, int out_size) {
    const float* q     = (const float*)d_in[0];
    const float* k     = (const float*)d_in[1];
    const float* v     = (const float*)d_in[2];
    const float* table = (const float*)d_in[3];
    float* out = (float*)d_out;

    bias_precompute_kernel<<<32, 256>>>(table);

    const int smem_bytes = 2 * BUF_FLOATS * sizeof(float);   // 106496 B
    cudaFuncSetAttribute(winattn_kernel,
                         cudaFuncAttributeMaxDynamicSharedMemorySize, smem_bytes);
    winattn_kernel<<<GRIDN, 128, smem_bytes>>>(q, k, v, out);
}

// round 12
// speedup vs baseline: 1.1523x; 1.1523x over previous
#include <cuda_runtime.h>
#include <cstdint>

// ----------------------------------------------------------------------------
// WindowAttention: 2048 windows x 8 heads, M=N=64, D=64, fp32.
// One CTA per (b,h); 128 threads / 4 warps; warp w owns query rows [16w,16w+16).
// Q fragments pulled to REGISTERS up-front -> V cp.async'd into the Q smem
// region at QK-mainloop START (hidden behind the whole QK+softmax phase).
// Regions: sA[64x68]: Q -> V ; sB[64x68]: K -> P -> O.  34.8 KB, 6 CTAs/SM.
// QK: Q exact tf32 hi+lo, K raw fp32 as tf32 (truncation). PV: P exact hi+lo,
// V raw. Bias pre-laid-out in fragment order (L2-resident). Rolled stores.
// ----------------------------------------------------------------------------

#define ASTR 68                       // mod 32 == 4
#define BSTR 68
#define BOFF 4352                     // 64*68
#define SM_FLOATS 8704                // 34816 B
#define SCALE_L2E 0.1803368801111146f // 0.125 * log2(e)

__device__ float4 g_biasF[8 * 4 * 8 * 32];   // [h][blk16][n][lane], * log2e

__global__ void bias_precompute_kernel(const float* __restrict__ table) {
    int t = blockIdx.x * blockDim.x + threadIdx.x;   // 0..8191
    if (t >= 8192) return;
    int h = t >> 10, blk = (t >> 8) & 3, n = (t >> 5) & 7, lane = t & 31;
    int g = lane >> 2, tig = lane & 3;
    int rA = 16 * blk + g, rB = rA + 8;
    int col = 8 * n + 2 * tig;
    const float L2E = 1.4426950408889634f;
    float4 r;
#define BIAS_AT(rr, cc, dst) {                                   \
        int raw = ((rr) - 32) * 128 + ((cc) - 32) + 64;          \
        int idx = raw < 0 ? raw + 16129 : raw;                   \
        dst = table[(size_t)idx * 8 + h] * L2E; }
    BIAS_AT(rA, col,     r.x);
    BIAS_AT(rA, col + 1, r.y);
    BIAS_AT(rB, col,     r.z);
    BIAS_AT(rB, col + 1, r.w);
#undef BIAS_AT
    g_biasF[t] = r;
}

__device__ __forceinline__ uint32_t f2tf32(float x) {
    uint32_t r;
    asm("cvt.rna.tf32.f32 %0, %1;" : "=r"(r) : "f"(x));
    return r;
}

__device__ __forceinline__ void split_tf32(float x, uint32_t& hi, uint32_t& lo) {
    hi = f2tf32(x);
    lo = f2tf32(x - __uint_as_float(hi));
}

__device__ __forceinline__ void mma_tf32(float c[4],
                                         uint32_t a0, uint32_t a1, uint32_t a2, uint32_t a3,
                                         uint32_t b0, uint32_t b1) {
    asm volatile(
        "mma.sync.aligned.m16n8k8.row.col.f32.tf32.tf32.f32 "
        "{%0,%1,%2,%3}, {%4,%5,%6,%7}, {%8,%9}, {%0,%1,%2,%3};"
        : "+f"(c[0]), "+f"(c[1]), "+f"(c[2]), "+f"(c[3])
        : "r"(a0), "r"(a1), "r"(a2), "r"(a3), "r"(b0), "r"(b1));
}

__device__ __forceinline__ void cp16(uint32_t smem_dst, const void* gmem_src) {
    asm volatile("cp.async.cg.shared.global [%0], [%1], 16;"
                 :: "r"(smem_dst), "l"(gmem_src));
}

__global__ __launch_bounds__(128, 6) void winattn_kernel(
    const float* __restrict__ q, const float* __restrict__ k,
    const float* __restrict__ v, float* __restrict__ out) {
    extern __shared__ float smem[];
    float* sA = smem;                    // Q, then V
    float* sB = smem + BOFF;             // K, then P, then O

    const int bh   = blockIdx.x;
    const int b    = bh >> 3;
    const int h    = bh & 7;
    const int tid  = threadIdx.x;
    const int lane = tid & 31;
    const int g    = lane >> 2;          // 0..7
    const int tig  = lane & 3;           // 0..3
    const int w    = tid >> 5;           // warp 0..3
    const int r0   = w * 16;             // warp's first query row

    const uint32_t sAu = (uint32_t)__cvta_generic_to_shared(sA);
    const uint32_t sBu = (uint32_t)__cvta_generic_to_shared(sB);

    // ---- async staging of raw Q, K ------------------------------------------
    {
        const float4* qg = (const float4*)(q + (size_t)bh * 4096);
        const float4* kg = (const float4*)(k + (size_t)bh * 4096);
#pragma unroll
        for (int j = 0; j < 8; ++j) {
            int i = tid + 128 * j;
            int m = i >> 4, c4 = i & 15;
            cp16(sAu + (m * ASTR + c4 * 4) * 4, qg + i);
            cp16(sBu + (m * BSTR + c4 * 4) * 4, kg + i);
        }
        asm volatile("cp.async.commit_group;");
        asm volatile("cp.async.wait_group 0;" ::: "memory");
    }
    __syncthreads();

    // ---- pull ALL Q fragments (32 floats) to registers; frees sA ------------
    float q0[8], q1[8], q2[8], q3[8];
#pragma unroll
    for (int ks = 0; ks < 8; ++ks) {
        const int kc = ks * 8 + tig;
        q0[ks] = sA[(r0 + g) * ASTR + kc];
        q1[ks] = sA[(r0 + g + 8) * ASTR + kc];
        q2[ks] = sA[(r0 + g) * ASTR + kc + 4];
        q3[ks] = sA[(r0 + g + 8) * ASTR + kc + 4];
    }
    __syncthreads();                     // all warps done reading Q from sA

    // ---- issue V -> sA NOW: hidden behind the whole QK mainloop -------------
    {
        const float4* vg = (const float4*)(v + (size_t)bh * 4096);
#pragma unroll
        for (int j = 0; j < 8; ++j) {
            int i = tid + 128 * j;
            int m = i >> 4, c4 = i & 15;
            cp16(sAu + (m * ASTR + c4 * 4) * 4, vg + i);
        }
        asm volatile("cp.async.commit_group;");
    }

    // ---- S = Q K^T : Q exact (hi+lo) from regs, K raw fp32 as tf32 ----------
    float c[8][4];
#pragma unroll
    for (int n = 0; n < 8; ++n) {
#pragma unroll
        for (int j = 0; j < 4; ++j) c[n][j] = 0.f;
    }

#pragma unroll
    for (int ks = 0; ks < 8; ++ks) {
        const int kc = ks * 8 + tig;
        uint32_t h0, l0, h1, l1, h2, l2, h3, l3;
        split_tf32(q0[ks], h0, l0);
        split_tf32(q1[ks], h1, l1);
        split_tf32(q2[ks], h2, l2);
        split_tf32(q3[ks], h3, l3);
#pragma unroll
        for (int n = 0; n < 8; ++n) {
            uint32_t b0 = __float_as_uint(sB[(n * 8 + g) * BSTR + kc]);
            uint32_t b1 = __float_as_uint(sB[(n * 8 + g) * BSTR + kc + 4]);
            mma_tf32(c[n], h0, h1, h2, h3, b0, b1);
            mma_tf32(c[n], l0, l1, l2, l3, b0, b1);
        }
    }

    // ---- scale + bias (fragment order, coalesced, L2-resident) --------------
    {
        const float4* bf = g_biasF + ((h * 4 + w) * 8) * 32 + lane;
#pragma unroll
        for (int n = 0; n < 8; ++n) {
            float4 bb = bf[n * 32];
            c[n][0] = fmaf(c[n][0], SCALE_L2E, bb.x);
            c[n][1] = fmaf(c[n][1], SCALE_L2E, bb.y);
            c[n][2] = fmaf(c[n][2], SCALE_L2E, bb.z);
            c[n][3] = fmaf(c[n][3], SCALE_L2E, bb.w);
        }
    }

    // ---- softmax (base-2 domain; quad holds a full row) ---------------------
    float mx0 = -1e30f, mx1 = -1e30f;
#pragma unroll
    for (int n = 0; n < 8; ++n) {
        mx0 = fmaxf(mx0, fmaxf(c[n][0], c[n][1]));
        mx1 = fmaxf(mx1, fmaxf(c[n][2], c[n][3]));
    }
#pragma unroll
    for (int d = 1; d <= 2; d <<= 1) {
        mx0 = fmaxf(mx0, __shfl_xor_sync(0xffffffffu, mx0, d));
        mx1 = fmaxf(mx1, __shfl_xor_sync(0xffffffffu, mx1, d));
    }
    float s0 = 0.f, s1 = 0.f;
#pragma unroll
    for (int n = 0; n < 8; ++n) {
        c[n][0] = exp2f(c[n][0] - mx0);
        c[n][1] = exp2f(c[n][1] - mx0);
        c[n][2] = exp2f(c[n][2] - mx1);
        c[n][3] = exp2f(c[n][3] - mx1);
        s0 += c[n][0] + c[n][1];
        s1 += c[n][2] + c[n][3];
    }
#pragma unroll
    for (int d = 1; d <= 2; d <<= 1) {
        s0 += __shfl_xor_sync(0xffffffffu, s0, d);
        s1 += __shfl_xor_sync(0xffffffffu, s1, d);
    }
    float inv0 = 1.0f / s0, inv1 = 1.0f / s1;

    // ---- all warps done with K; stage unnormalized P over sB ----------------
    __syncthreads();
#pragma unroll
    for (int n = 0; n < 8; ++n) {
        int col = n * 8 + 2 * tig;
        *(float2*)(sB + (r0 + g) * BSTR + col)     = make_float2(c[n][0], c[n][1]);
        *(float2*)(sB + (r0 + g + 8) * BSTR + col) = make_float2(c[n][2], c[n][3]);
    }
    __syncwarp();

    // ---- ensure V landed (should be long since) ------------------------------
    asm volatile("cp.async.wait_group 0;" ::: "memory");
    __syncthreads();

    // ---- O = P V : P exact (hi+lo), V raw (2-way-conflict LDS, acceptable) ---
    float o[8][4];
#pragma unroll
    for (int d = 0; d < 8; ++d) {
#pragma unroll
        for (int j = 0; j < 4; ++j) o[d][j] = 0.f;
    }
#pragma unroll
    for (int ks = 0; ks < 8; ++ks) {
        const int kc = ks * 8 + tig;
        uint32_t h0, l0, h1, l1, h2, l2, h3, l3;
        split_tf32(sB[(r0 + g) * BSTR + kc],         h0, l0);
        split_tf32(sB[(r0 + g + 8) * BSTR + kc],     h1, l1);
        split_tf32(sB[(r0 + g) * BSTR + kc + 4],     h2, l2);
        split_tf32(sB[(r0 + g + 8) * BSTR + kc + 4], h3, l3);
#pragma unroll
        for (int dt = 0; dt < 8; ++dt) {
            uint32_t b0 = __float_as_uint(sA[(ks * 8 + tig) * ASTR + dt * 8 + g]);
            uint32_t b1 = __float_as_uint(sA[(ks * 8 + tig + 4) * ASTR + dt * 8 + g]);
            mma_tf32(o[dt], h0, h1, h2, h3, b0, b1);
            mma_tf32(o[dt], l0, l1, l2, l3, b0, b1);
        }
    }

    // ---- stage normalized O over own P rows, then coalesced rolled stores ----
    __syncwarp();
#pragma unroll
    for (int dt = 0; dt < 8; ++dt) {
        int col = dt * 8 + 2 * tig;
        *(float2*)(sB + (r0 + g) * BSTR + col)     = make_float2(o[dt][0] * inv0, o[dt][1] * inv0);
        *(float2*)(sB + (r0 + g + 8) * BSTR + col) = make_float2(o[dt][2] * inv1, o[dt][3] * inv1);
    }
    __syncthreads();

    {
        float* ob = out + (size_t)b * 32768;
        const int cbase = h * 64 - 32;
        const int c4 = tid & 15;            // 16 float4 per row
        const int col = (cbase + 4 * c4) & 511;
#pragma unroll
        for (int it = 0; it < 8; ++it) {
            int row = (tid >> 4) + 8 * it;
            float4 val = *(const float4*)(sB + row * BSTR + c4 * 4);
            *(float4*)(ob + row * 512 + col) = val;
        }
    }
}

extern "C" void kernel_launch(void* const* d_in, const int* in_sizes, int n_in,
                              void* d_out, int out_size) {
    const float* q     = (const float*)d_in[0];
    const float* k     = (const float*)d_in[1];
    const float* v     = (const float*)d_in[2];
    const float* table = (const float*)d_in[3];
    float* out = (float*)d_out;

    bias_precompute_kernel<<<32, 256>>>(table);

    const int smem_bytes = SM_FLOATS * sizeof(float);   // 34816 B
    cudaFuncSetAttribute(winattn_kernel,
                         cudaFuncAttributeMaxDynamicSharedMemorySize, smem_bytes);
    winattn_kernel<<<16384, 128, smem_bytes>>>(q, k, v, out);
}

// round 13
// speedup vs baseline: 1.1850x; 1.0284x over previous
#include <cuda_runtime.h>
#include <cstdint>

// ----------------------------------------------------------------------------
// WindowAttention: 2048 windows x 8 heads, M=N=64, D=64, fp32.
// One CTA per (b,h); 128 threads / 4 warps; warp w owns query rows [16w,16w+16).
// Q fragments pulled to REGISTERS up-front -> V cp.async'd into the Q smem
// region at QK-mainloop START (hidden behind the whole QK+softmax phase).
// sA region is 64x72: Q staged at stride 68 (conflict-free frag reads),
// V staged at stride 72 (conflict-free frag reads). sB[64x68]: K -> P -> O.
// 35.8 KB smem -> 6 CTAs/SM. QK: Q exact tf32 hi+lo, K raw fp32 as tf32.
// PV: P exact hi+lo, V raw. Bias in fragment order (L2). Rolled stores.
// ----------------------------------------------------------------------------

#define QSTR 68                       // mod 32 == 4 -> bank 4g+tig, conflict-free
#define BSTR 68
#define VSTR 72                       // mod 32 == 8 -> bank 8(tig+dt)+g, conflict-free
#define BOFF 4608                     // sA sized 64*72 floats
#define SM_FLOATS (4608 + 4352)      // 8960 floats = 35840 B
#define SCALE_L2E 0.1803368801111146f // 0.125 * log2(e)

__device__ float4 g_biasF[8 * 4 * 8 * 32];   // [h][blk16][n][lane], * log2e

__global__ void bias_precompute_kernel(const float* __restrict__ table) {
    int t = blockIdx.x * blockDim.x + threadIdx.x;   // 0..8191
    if (t >= 8192) return;
    int h = t >> 10, blk = (t >> 8) & 3, n = (t >> 5) & 7, lane = t & 31;
    int g = lane >> 2, tig = lane & 3;
    int rA = 16 * blk + g, rB = rA + 8;
    int col = 8 * n + 2 * tig;
    const float L2E = 1.4426950408889634f;
    float4 r;
#define BIAS_AT(rr, cc, dst) {                                   \
        int raw = ((rr) - 32) * 128 + ((cc) - 32) + 64;          \
        int idx = raw < 0 ? raw + 16129 : raw;                   \
        dst = table[(size_t)idx * 8 + h] * L2E; }
    BIAS_AT(rA, col,     r.x);
    BIAS_AT(rA, col + 1, r.y);
    BIAS_AT(rB, col,     r.z);
    BIAS_AT(rB, col + 1, r.w);
#undef BIAS_AT
    g_biasF[t] = r;
}

__device__ __forceinline__ uint32_t f2tf32(float x) {
    uint32_t r;
    asm("cvt.rna.tf32.f32 %0, %1;" : "=r"(r) : "f"(x));
    return r;
}

__device__ __forceinline__ void split_tf32(float x, uint32_t& hi, uint32_t& lo) {
    hi = f2tf32(x);
    lo = f2tf32(x - __uint_as_float(hi));
}

__device__ __forceinline__ void mma_tf32(float c[4],
                                         uint32_t a0, uint32_t a1, uint32_t a2, uint32_t a3,
                                         uint32_t b0, uint32_t b1) {
    asm volatile(
        "mma.sync.aligned.m16n8k8.row.col.f32.tf32.tf32.f32 "
        "{%0,%1,%2,%3}, {%4,%5,%6,%7}, {%8,%9}, {%0,%1,%2,%3};"
        : "+f"(c[0]), "+f"(c[1]), "+f"(c[2]), "+f"(c[3])
        : "r"(a0), "r"(a1), "r"(a2), "r"(a3), "r"(b0), "r"(b1));
}

__device__ __forceinline__ void cp16(uint32_t smem_dst, const void* gmem_src) {
    asm volatile("cp.async.cg.shared.global [%0], [%1], 16;"
                 :: "r"(smem_dst), "l"(gmem_src));
}

__global__ __launch_bounds__(128, 6) void winattn_kernel(
    const float* __restrict__ q, const float* __restrict__ k,
    const float* __restrict__ v, float* __restrict__ out) {
    extern __shared__ float smem[];
    float* sA = smem;                    // Q (stride 68), then V (stride 72)
    float* sB = smem + BOFF;             // K, then P, then O (stride 68)

    const int bh   = blockIdx.x;
    const int b    = bh >> 3;
    const int h    = bh & 7;
    const int tid  = threadIdx.x;
    const int lane = tid & 31;
    const int g    = lane >> 2;          // 0..7
    const int tig  = lane & 3;           // 0..3
    const int w    = tid >> 5;           // warp 0..3
    const int r0   = w * 16;             // warp's first query row

    const uint32_t sAu = (uint32_t)__cvta_generic_to_shared(sA);
    const uint32_t sBu = (uint32_t)__cvta_generic_to_shared(sB);

    // ---- async staging of raw Q (stride 68), K (stride 68) ------------------
    {
        const float4* qg = (const float4*)(q + (size_t)bh * 4096);
        const float4* kg = (const float4*)(k + (size_t)bh * 4096);
#pragma unroll
        for (int j = 0; j < 8; ++j) {
            int i = tid + 128 * j;
            int m = i >> 4, c4 = i & 15;
            cp16(sAu + (m * QSTR + c4 * 4) * 4, qg + i);
            cp16(sBu + (m * BSTR + c4 * 4) * 4, kg + i);
        }
        asm volatile("cp.async.commit_group;");
        asm volatile("cp.async.wait_group 0;" ::: "memory");
    }
    __syncthreads();

    // ---- pull ALL Q fragments (32 floats) to registers; frees sA ------------
    float q0[8], q1[8], q2[8], q3[8];
#pragma unroll
    for (int ks = 0; ks < 8; ++ks) {
        const int kc = ks * 8 + tig;
        q0[ks] = sA[(r0 + g) * QSTR + kc];
        q1[ks] = sA[(r0 + g + 8) * QSTR + kc];
        q2[ks] = sA[(r0 + g) * QSTR + kc + 4];
        q3[ks] = sA[(r0 + g + 8) * QSTR + kc + 4];
    }
    __syncthreads();                     // all warps done reading Q from sA

    // ---- issue V -> sA at stride 72 NOW (hidden behind QK mainloop) ---------
    {
        const float4* vg = (const float4*)(v + (size_t)bh * 4096);
#pragma unroll
        for (int j = 0; j < 8; ++j) {
            int i = tid + 128 * j;
            int m = i >> 4, c4 = i & 15;
            cp16(sAu + (m * VSTR + c4 * 4) * 4, vg + i);
        }
        asm volatile("cp.async.commit_group;");
    }

    // ---- S = Q K^T : Q exact (hi+lo) from regs, K raw fp32 as tf32 ----------
    float c[8][4];
#pragma unroll
    for (int n = 0; n < 8; ++n) {
#pragma unroll
        for (int j = 0; j < 4; ++j) c[n][j] = 0.f;
    }

#pragma unroll
    for (int ks = 0; ks < 8; ++ks) {
        const int kc = ks * 8 + tig;
        uint32_t h0, l0, h1, l1, h2, l2, h3, l3;
        split_tf32(q0[ks], h0, l0);
        split_tf32(q1[ks], h1, l1);
        split_tf32(q2[ks], h2, l2);
        split_tf32(q3[ks], h3, l3);
#pragma unroll
        for (int n = 0; n < 8; ++n) {
            uint32_t b0 = __float_as_uint(sB[(n * 8 + g) * BSTR + kc]);
            uint32_t b1 = __float_as_uint(sB[(n * 8 + g) * BSTR + kc + 4]);
            mma_tf32(c[n], h0, h1, h2, h3, b0, b1);
            mma_tf32(c[n], l0, l1, l2, l3, b0, b1);
        }
    }

    // ---- scale + bias (fragment order, coalesced, L2-resident) --------------
    {
        const float4* bf = g_biasF + ((h * 4 + w) * 8) * 32 + lane;
#pragma unroll
        for (int n = 0; n < 8; ++n) {
            float4 bb = bf[n * 32];
            c[n][0] = fmaf(c[n][0], SCALE_L2E, bb.x);
            c[n][1] = fmaf(c[n][1], SCALE_L2E, bb.y);
            c[n][2] = fmaf(c[n][2], SCALE_L2E, bb.z);
            c[n][3] = fmaf(c[n][3], SCALE_L2E, bb.w);
        }
    }

    // ---- softmax (base-2 domain; quad holds a full row) ---------------------
    float mx0 = -1e30f, mx1 = -1e30f;
#pragma unroll
    for (int n = 0; n < 8; ++n) {
        mx0 = fmaxf(mx0, fmaxf(c[n][0], c[n][1]));
        mx1 = fmaxf(mx1, fmaxf(c[n][2], c[n][3]));
    }
#pragma unroll
    for (int d = 1; d <= 2; d <<= 1) {
        mx0 = fmaxf(mx0, __shfl_xor_sync(0xffffffffu, mx0, d));
        mx1 = fmaxf(mx1, __shfl_xor_sync(0xffffffffu, mx1, d));
    }
    float s0 = 0.f, s1 = 0.f;
#pragma unroll
    for (int n = 0; n < 8; ++n) {
        c[n][0] = exp2f(c[n][0] - mx0);
        c[n][1] = exp2f(c[n][1] - mx0);
        c[n][2] = exp2f(c[n][2] - mx1);
        c[n][3] = exp2f(c[n][3] - mx1);
        s0 += c[n][0] + c[n][1];
        s1 += c[n][2] + c[n][3];
    }
#pragma unroll
    for (int d = 1; d <= 2; d <<= 1) {
        s0 += __shfl_xor_sync(0xffffffffu, s0, d);
        s1 += __shfl_xor_sync(0xffffffffu, s1, d);
    }
    float inv0 = 1.0f / s0, inv1 = 1.0f / s1;

    // ---- all warps done with K; stage unnormalized P over sB ----------------
    __syncthreads();
#pragma unroll
    for (int n = 0; n < 8; ++n) {
        int col = n * 8 + 2 * tig;
        *(float2*)(sB + (r0 + g) * BSTR + col)     = make_float2(c[n][0], c[n][1]);
        *(float2*)(sB + (r0 + g + 8) * BSTR + col) = make_float2(c[n][2], c[n][3]);
    }
    __syncwarp();

    // ---- ensure V landed (should be long since) ------------------------------
    asm volatile("cp.async.wait_group 0;" ::: "memory");
    __syncthreads();

    // ---- O = P V : P exact (hi+lo), V raw at stride 72 (conflict-free) ------
    float o[8][4];
#pragma unroll
    for (int d = 0; d < 8; ++d) {
#pragma unroll
        for (int j = 0; j < 4; ++j) o[d][j] = 0.f;
    }
#pragma unroll
    for (int ks = 0; ks < 8; ++ks) {
        const int kc = ks * 8 + tig;
        uint32_t h0, l0, h1, l1, h2, l2, h3, l3;
        split_tf32(sB[(r0 + g) * BSTR + kc],         h0, l0);
        split_tf32(sB[(r0 + g + 8) * BSTR + kc],     h1, l1);
        split_tf32(sB[(r0 + g) * BSTR + kc + 4],     h2, l2);
        split_tf32(sB[(r0 + g + 8) * BSTR + kc + 4], h3, l3);
#pragma unroll
        for (int dt = 0; dt < 8; ++dt) {
            uint32_t b0 = __float_as_uint(sA[(ks * 8 + tig) * VSTR + dt * 8 + g]);
            uint32_t b1 = __float_as_uint(sA[(ks * 8 + tig + 4) * VSTR + dt * 8 + g]);
            mma_tf32(o[dt], h0, h1, h2, h3, b0, b1);
            mma_tf32(o[dt], l0, l1, l2, l3, b0, b1);
        }
    }

    // ---- stage normalized O over own P rows, then coalesced rolled stores ----
    __syncwarp();
#pragma unroll
    for (int dt = 0; dt < 8; ++dt) {
        int col = dt * 8 + 2 * tig;
        *(float2*)(sB + (r0 + g) * BSTR + col)     = make_float2(o[dt][0] * inv0, o[dt][1] * inv0);
        *(float2*)(sB + (r0 + g + 8) * BSTR + col) = make_float2(o[dt][2] * inv1, o[dt][3] * inv1);
    }
    __syncthreads();

    {
        float* ob = out + (size_t)b * 32768;
        const int cbase = h * 64 - 32;
        const int c4 = tid & 15;            // 16 float4 per row
        const int col = (cbase + 4 * c4) & 511;
#pragma unroll
        for (int it = 0; it < 8; ++it) {
            int row = (tid >> 4) + 8 * it;
            float4 val = *(const float4*)(sB + row * BSTR + c4 * 4);
            *(float4*)(ob + row * 512 + col) = val;
        }
    }
}

extern "C" void kernel_launch(void* const* d_in, const int* in_sizes, int n_in,
                              void* d_out, int out_size) {
    const float* q     = (const float*)d_in[0];
    const float* k     = (const float*)d_in[1];
    const float* v     = (const float*)d_in[2];
    const float* table = (const float*)d_in[3];
    float* out = (float*)d_out;

    bias_precompute_kernel<<<32, 256>>>(table);

    const int smem_bytes = SM_FLOATS * sizeof(float);   // 35840 B
    cudaFuncSetAttribute(winattn_kernel,
                         cudaFuncAttributeMaxDynamicSharedMemorySize, smem_bytes);
    winattn_kernel<<<16384, 128, smem_bytes>>>(q, k, v, out);
}

// round 14
// speedup vs baseline: 1.3423x; 1.1328x over previous
#include <cuda_runtime.h>
#include <cstdint>

// ----------------------------------------------------------------------------
// WindowAttention: 2048 windows x 8 heads, M=N=64, D=64, fp32.
// One CTA per (b,h); 128 threads / 4 warps; warp w owns query rows [16w,16w+16).
// Q fragments pulled to REGISTERS up-front -> V cp.async'd into the Q smem
// region at QK-mainloop START (hidden behind the whole QK+softmax phase).
// sA region 64x72: Q staged at stride 68, V at stride 72 (both conflict-free).
// sB[64x68]: K -> P -> O. 35.8 KB smem -> 6 CTAs/SM.
// QK: Q exact tf32 hi+lo, K raw fp32 as tf32 (truncation).
// PV: P SINGLE tf32 (rna), V raw  -> 25% fewer HMMAs than R13.
// Bias in fragment order (L2-resident). Rolled coalesced stores.
// ----------------------------------------------------------------------------

#define QSTR 68                       // mod 32 == 4 -> bank 4g+tig, conflict-free
#define BSTR 68
#define VSTR 72                       // mod 32 == 8 -> bank 8(tig+dt)+g, conflict-free
#define BOFF 4608                     // sA sized 64*72 floats
#define SM_FLOATS (4608 + 4352)       // 8960 floats = 35840 B
#define SCALE_L2E 0.1803368801111146f // 0.125 * log2(e)

__device__ float4 g_biasF[8 * 4 * 8 * 32];   // [h][blk16][n][lane], * log2e

__global__ void bias_precompute_kernel(const float* __restrict__ table) {
    int t = blockIdx.x * blockDim.x + threadIdx.x;   // 0..8191
    if (t >= 8192) return;
    int h = t >> 10, blk = (t >> 8) & 3, n = (t >> 5) & 7, lane = t & 31;
    int g = lane >> 2, tig = lane & 3;
    int rA = 16 * blk + g, rB = rA + 8;
    int col = 8 * n + 2 * tig;
    const float L2E = 1.4426950408889634f;
    float4 r;
#define BIAS_AT(rr, cc, dst) {                                   \
        int raw = ((rr) - 32) * 128 + ((cc) - 32) + 64;          \
        int idx = raw < 0 ? raw + 16129 : raw;                   \
        dst = table[(size_t)idx * 8 + h] * L2E; }
    BIAS_AT(rA, col,     r.x);
    BIAS_AT(rA, col + 1, r.y);
    BIAS_AT(rB, col,     r.z);
    BIAS_AT(rB, col + 1, r.w);
#undef BIAS_AT
    g_biasF[t] = r;
}

__device__ __forceinline__ uint32_t f2tf32(float x) {
    uint32_t r;
    asm("cvt.rna.tf32.f32 %0, %1;" : "=r"(r) : "f"(x));
    return r;
}

__device__ __forceinline__ void split_tf32(float x, uint32_t& hi, uint32_t& lo) {
    hi = f2tf32(x);
    lo = f2tf32(x - __uint_as_float(hi));
}

__device__ __forceinline__ void mma_tf32(float c[4],
                                         uint32_t a0, uint32_t a1, uint32_t a2, uint32_t a3,
                                         uint32_t b0, uint32_t b1) {
    asm volatile(
        "mma.sync.aligned.m16n8k8.row.col.f32.tf32.tf32.f32 "
        "{%0,%1,%2,%3}, {%4,%5,%6,%7}, {%8,%9}, {%0,%1,%2,%3};"
        : "+f"(c[0]), "+f"(c[1]), "+f"(c[2]), "+f"(c[3])
        : "r"(a0), "r"(a1), "r"(a2), "r"(a3), "r"(b0), "r"(b1));
}

__device__ __forceinline__ void cp16(uint32_t smem_dst, const void* gmem_src) {
    asm volatile("cp.async.cg.shared.global [%0], [%1], 16;"
                 :: "r"(smem_dst), "l"(gmem_src));
}

__global__ __launch_bounds__(128, 6) void winattn_kernel(
    const float* __restrict__ q, const float* __restrict__ k,
    const float* __restrict__ v, float* __restrict__ out) {
    extern __shared__ float smem[];
    float* sA = smem;                    // Q (stride 68), then V (stride 72)
    float* sB = smem + BOFF;             // K, then P, then O (stride 68)

    const int bh   = blockIdx.x;
    const int b    = bh >> 3;
    const int h    = bh & 7;
    const int tid  = threadIdx.x;
    const int lane = tid & 31;
    const int g    = lane >> 2;          // 0..7
    const int tig  = lane & 3;           // 0..3
    const int w    = tid >> 5;           // warp 0..3
    const int r0   = w * 16;             // warp's first query row

    const uint32_t sAu = (uint32_t)__cvta_generic_to_shared(sA);
    const uint32_t sBu = (uint32_t)__cvta_generic_to_shared(sB);

    // ---- async staging of raw Q (stride 68), K (stride 68) ------------------
    {
        const float4* qg = (const float4*)(q + (size_t)bh * 4096);
        const float4* kg = (const float4*)(k + (size_t)bh * 4096);
#pragma unroll
        for (int j = 0; j < 8; ++j) {
            int i = tid + 128 * j;
            int m = i >> 4, c4 = i & 15;
            cp16(sAu + (m * QSTR + c4 * 4) * 4, qg + i);
            cp16(sBu + (m * BSTR + c4 * 4) * 4, kg + i);
        }
        asm volatile("cp.async.commit_group;");
        asm volatile("cp.async.wait_group 0;" ::: "memory");
    }
    __syncthreads();

    // ---- pull ALL Q fragments (32 floats) to registers; frees sA ------------
    float q0[8], q1[8], q2[8], q3[8];
#pragma unroll
    for (int ks = 0; ks < 8; ++ks) {
        const int kc = ks * 8 + tig;
        q0[ks] = sA[(r0 + g) * QSTR + kc];
        q1[ks] = sA[(r0 + g + 8) * QSTR + kc];
        q2[ks] = sA[(r0 + g) * QSTR + kc + 4];
        q3[ks] = sA[(r0 + g + 8) * QSTR + kc + 4];
    }
    __syncthreads();                     // all warps done reading Q from sA

    // ---- issue V -> sA at stride 72 NOW (hidden behind QK mainloop) ---------
    {
        const float4* vg = (const float4*)(v + (size_t)bh * 4096);
#pragma unroll
        for (int j = 0; j < 8; ++j) {
            int i = tid + 128 * j;
            int m = i >> 4, c4 = i & 15;
            cp16(sAu + (m * VSTR + c4 * 4) * 4, vg + i);
        }
        asm volatile("cp.async.commit_group;");
    }

    // ---- S = Q K^T : Q exact (hi+lo) from regs, K raw fp32 as tf32 ----------
    float c[8][4];
#pragma unroll
    for (int n = 0; n < 8; ++n) {
#pragma unroll
        for (int j = 0; j < 4; ++j) c[n][j] = 0.f;
    }

#pragma unroll
    for (int ks = 0; ks < 8; ++ks) {
        const int kc = ks * 8 + tig;
        uint32_t h0, l0, h1, l1, h2, l2, h3, l3;
        split_tf32(q0[ks], h0, l0);
        split_tf32(q1[ks], h1, l1);
        split_tf32(q2[ks], h2, l2);
        split_tf32(q3[ks], h3, l3);
#pragma unroll
        for (int n = 0; n < 8; ++n) {
            uint32_t b0 = __float_as_uint(sB[(n * 8 + g) * BSTR + kc]);
            uint32_t b1 = __float_as_uint(sB[(n * 8 + g) * BSTR + kc + 4]);
            mma_tf32(c[n], h0, h1, h2, h3, b0, b1);
            mma_tf32(c[n], l0, l1, l2, l3, b0, b1);
        }
    }

    // ---- scale + bias (fragment order, coalesced, L2-resident) --------------
    {
        const float4* bf = g_biasF + ((h * 4 + w) * 8) * 32 + lane;
#pragma unroll
        for (int n = 0; n < 8; ++n) {
            float4 bb = bf[n * 32];
            c[n][0] = fmaf(c[n][0], SCALE_L2E, bb.x);
            c[n][1] = fmaf(c[n][1], SCALE_L2E, bb.y);
            c[n][2] = fmaf(c[n][2], SCALE_L2E, bb.z);
            c[n][3] = fmaf(c[n][3], SCALE_L2E, bb.w);
        }
    }

    // ---- softmax (base-2 domain; quad holds a full row) ---------------------
    float mx0 = -1e30f, mx1 = -1e30f;
#pragma unroll
    for (int n = 0; n < 8; ++n) {
        mx0 = fmaxf(mx0, fmaxf(c[n][0], c[n][1]));
        mx1 = fmaxf(mx1, fmaxf(c[n][2], c[n][3]));
    }
#pragma unroll
    for (int d = 1; d <= 2; d <<= 1) {
        mx0 = fmaxf(mx0, __shfl_xor_sync(0xffffffffu, mx0, d));
        mx1 = fmaxf(mx1, __shfl_xor_sync(0xffffffffu, mx1, d));
    }
    float s0 = 0.f, s1 = 0.f;
#pragma unroll
    for (int n = 0; n < 8; ++n) {
        c[n][0] = exp2f(c[n][0] - mx0);
        c[n][1] = exp2f(c[n][1] - mx0);
        c[n][2] = exp2f(c[n][2] - mx1);
        c[n][3] = exp2f(c[n][3] - mx1);
        s0 += c[n][0] + c[n][1];
        s1 += c[n][2] + c[n][3];
    }
#pragma unroll
    for (int d = 1; d <= 2; d <<= 1) {
        s0 += __shfl_xor_sync(0xffffffffu, s0, d);
        s1 += __shfl_xor_sync(0xffffffffu, s1, d);
    }
    float inv0 = 1.0f / s0, inv1 = 1.0f / s1;

    // ---- all warps done with K; stage unnormalized P over sB ----------------
    __syncthreads();
#pragma unroll
    for (int n = 0; n < 8; ++n) {
        int col = n * 8 + 2 * tig;
        *(float2*)(sB + (r0 + g) * BSTR + col)     = make_float2(c[n][0], c[n][1]);
        *(float2*)(sB + (r0 + g + 8) * BSTR + col) = make_float2(c[n][2], c[n][3]);
    }
    __syncwarp();

    // ---- ensure V landed (should be long since) ------------------------------
    asm volatile("cp.async.wait_group 0;" ::: "memory");
    __syncthreads();

    // ---- O = P V : P SINGLE tf32 (rna), V raw at stride 72 -------------------
    float o[8][4];
#pragma unroll
    for (int d = 0; d < 8; ++d) {
#pragma unroll
        for (int j = 0; j < 4; ++j) o[d][j] = 0.f;
    }
#pragma unroll
    for (int ks = 0; ks < 8; ++ks) {
        const int kc = ks * 8 + tig;
        uint32_t h0 = f2tf32(sB[(r0 + g) * BSTR + kc]);
        uint32_t h1 = f2tf32(sB[(r0 + g + 8) * BSTR + kc]);
        uint32_t h2 = f2tf32(sB[(r0 + g) * BSTR + kc + 4]);
        uint32_t h3 = f2tf32(sB[(r0 + g + 8) * BSTR + kc + 4]);
#pragma unroll
        for (int dt = 0; dt < 8; ++dt) {
            uint32_t b0 = __float_as_uint(sA[(ks * 8 + tig) * VSTR + dt * 8 + g]);
            uint32_t b1 = __float_as_uint(sA[(ks * 8 + tig + 4) * VSTR + dt * 8 + g]);
            mma_tf32(o[dt], h0, h1, h2, h3, b0, b1);
        }
    }

    // ---- stage normalized O over own P rows, then coalesced rolled stores ----
    __syncwarp();
#pragma unroll
    for (int dt = 0; dt < 8; ++dt) {
        int col = dt * 8 + 2 * tig;
        *(float2*)(sB + (r0 + g) * BSTR + col)     = make_float2(o[dt][0] * inv0, o[dt][1] * inv0);
        *(float2*)(sB + (r0 + g + 8) * BSTR + col) = make_float2(o[dt][2] * inv1, o[dt][3] * inv1);
    }
    __syncthreads();

    {
        float* ob = out + (size_t)b * 32768;
        const int cbase = h * 64 - 32;
        const int c4 = tid & 15;            // 16 float4 per row
        const int col = (cbase + 4 * c4) & 511;
#pragma unroll
        for (int it = 0; it < 8; ++it) {
            int row = (tid >> 4) + 8 * it;
            float4 val = *(const float4*)(sB + row * BSTR + c4 * 4);
            *(float4*)(ob + row * 512 + col) = val;
        }
    }
}

extern "C" void kernel_launch(void* const* d_in, const int* in_sizes, int n_in,
                              void* d_out, int out_size) {
    const float* q     = (const float*)d_in[0];
    const float* k     = (const float*)d_in[1];
    const float* v     = (const float*)d_in[2];
    const float* table = (const float*)d_in[3];
    float* out = (float*)d_out;

    bias_precompute_kernel<<<32, 256>>>(table);

    const int smem_bytes = SM_FLOATS * sizeof(float);   // 35840 B
    cudaFuncSetAttribute(winattn_kernel,
                         cudaFuncAttributeMaxDynamicSharedMemorySize, smem_bytes);
    winattn_kernel<<<16384, 128, smem_bytes>>>(q, k, v, out);
}

// round 15
// speedup vs baseline: 1.4079x; 1.0489x over previous
#include <cuda_runtime.h>
#include <cstdint>

// ----------------------------------------------------------------------------
// WindowAttention: 2048 windows x 8 heads, M=N=64, D=64, fp32.
// One CTA per (b,h); 128 threads / 4 warps; warp w owns query rows [16w,16w+16).
// Q fragments pulled to REGISTERS up-front -> V cp.async'd into the Q smem
// region at QK-mainloop START (hidden behind the whole QK+softmax phase).
// sA region 64x72: Q staged at stride 68, V at stride 72 (both conflict-free).
// sB[64x68]: K -> P -> O. 35.8 KB smem -> 6 CTAs/SM.
// QK: Q SINGLE tf32 (rna), K raw fp32 as tf32 (truncation)  [was hi+lo in R14]
// PV: P SINGLE tf32 (rna), V raw.  128 HMMAs/warp total (-33% vs R14).
// Bias in fragment order (L2-resident). Rolled coalesced stores.
// ----------------------------------------------------------------------------

#define QSTR 68                       // mod 32 == 4 -> bank 4g+tig, conflict-free
#define BSTR 68
#define VSTR 72                       // mod 32 == 8 -> bank 8(tig+dt)+g, conflict-free
#define BOFF 4608                     // sA sized 64*72 floats
#define SM_FLOATS (4608 + 4352)       // 8960 floats = 35840 B
#define SCALE_L2E 0.1803368801111146f // 0.125 * log2(e)

__device__ float4 g_biasF[8 * 4 * 8 * 32];   // [h][blk16][n][lane], * log2e

__global__ void bias_precompute_kernel(const float* __restrict__ table) {
    int t = blockIdx.x * blockDim.x + threadIdx.x;   // 0..8191
    if (t >= 8192) return;
    int h = t >> 10, blk = (t >> 8) & 3, n = (t >> 5) & 7, lane = t & 31;
    int g = lane >> 2, tig = lane & 3;
    int rA = 16 * blk + g, rB = rA + 8;
    int col = 8 * n + 2 * tig;
    const float L2E = 1.4426950408889634f;
    float4 r;
#define BIAS_AT(rr, cc, dst) {                                   \
        int raw = ((rr) - 32) * 128 + ((cc) - 32) + 64;          \
        int idx = raw < 0 ? raw + 16129 : raw;                   \
        dst = table[(size_t)idx * 8 + h] * L2E; }
    BIAS_AT(rA, col,     r.x);
    BIAS_AT(rA, col + 1, r.y);
    BIAS_AT(rB, col,     r.z);
    BIAS_AT(rB, col + 1, r.w);
#undef BIAS_AT
    g_biasF[t] = r;
}

__device__ __forceinline__ uint32_t f2tf32(float x) {
    uint32_t r;
    asm("cvt.rna.tf32.f32 %0, %1;" : "=r"(r) : "f"(x));
    return r;
}

__device__ __forceinline__ void mma_tf32(float c[4],
                                         uint32_t a0, uint32_t a1, uint32_t a2, uint32_t a3,
                                         uint32_t b0, uint32_t b1) {
    asm volatile(
        "mma.sync.aligned.m16n8k8.row.col.f32.tf32.tf32.f32 "
        "{%0,%1,%2,%3}, {%4,%5,%6,%7}, {%8,%9}, {%0,%1,%2,%3};"
        : "+f"(c[0]), "+f"(c[1]), "+f"(c[2]), "+f"(c[3])
        : "r"(a0), "r"(a1), "r"(a2), "r"(a3), "r"(b0), "r"(b1));
}

__device__ __forceinline__ void cp16(uint32_t smem_dst, const void* gmem_src) {
    asm volatile("cp.async.cg.shared.global [%0], [%1], 16;"
                 :: "r"(smem_dst), "l"(gmem_src));
}

__global__ __launch_bounds__(128, 6) void winattn_kernel(
    const float* __restrict__ q, const float* __restrict__ k,
    const float* __restrict__ v, float* __restrict__ out) {
    extern __shared__ float smem[];
    float* sA = smem;                    // Q (stride 68), then V (stride 72)
    float* sB = smem + BOFF;             // K, then P, then O (stride 68)

    const int bh   = blockIdx.x;
    const int b    = bh >> 3;
    const int h    = bh & 7;
    const int tid  = threadIdx.x;
    const int lane = tid & 31;
    const int g    = lane >> 2;          // 0..7
    const int tig  = lane & 3;           // 0..3
    const int w    = tid >> 5;           // warp 0..3
    const int r0   = w * 16;             // warp's first query row

    const uint32_t sAu = (uint32_t)__cvta_generic_to_shared(sA);
    const uint32_t sBu = (uint32_t)__cvta_generic_to_shared(sB);

    // ---- async staging of raw Q (stride 68), K (stride 68) ------------------
    {
        const float4* qg = (const float4*)(q + (size_t)bh * 4096);
        const float4* kg = (const float4*)(k + (size_t)bh * 4096);
#pragma unroll
        for (int j = 0; j < 8; ++j) {
            int i = tid + 128 * j;
            int m = i >> 4, c4 = i & 15;
            cp16(sAu + (m * QSTR + c4 * 4) * 4, qg + i);
            cp16(sBu + (m * BSTR + c4 * 4) * 4, kg + i);
        }
        asm volatile("cp.async.commit_group;");
        asm volatile("cp.async.wait_group 0;" ::: "memory");
    }
    __syncthreads();

    // ---- pull ALL Q fragments to registers as tf32 (rna); frees sA ----------
    uint32_t tq0[8], tq1[8], tq2[8], tq3[8];
#pragma unroll
    for (int ks = 0; ks < 8; ++ks) {
        const int kc = ks * 8 + tig;
        tq0[ks] = f2tf32(sA[(r0 + g) * QSTR + kc]);
        tq1[ks] = f2tf32(sA[(r0 + g + 8) * QSTR + kc]);
        tq2[ks] = f2tf32(sA[(r0 + g) * QSTR + kc + 4]);
        tq3[ks] = f2tf32(sA[(r0 + g + 8) * QSTR + kc + 4]);
    }
    __syncthreads();                     // all warps done reading Q from sA

    // ---- issue V -> sA at stride 72 NOW (hidden behind QK mainloop) ---------
    {
        const float4* vg = (const float4*)(v + (size_t)bh * 4096);
#pragma unroll
        for (int j = 0; j < 8; ++j) {
            int i = tid + 128 * j;
            int m = i >> 4, c4 = i & 15;
            cp16(sAu + (m * VSTR + c4 * 4) * 4, vg + i);
        }
        asm volatile("cp.async.commit_group;");
    }

    // ---- S = Q K^T : Q single tf32 (rna), K raw fp32 as tf32 ----------------
    float c[8][4];
#pragma unroll
    for (int n = 0; n < 8; ++n) {
#pragma unroll
        for (int j = 0; j < 4; ++j) c[n][j] = 0.f;
    }

#pragma unroll
    for (int ks = 0; ks < 8; ++ks) {
        const int kc = ks * 8 + tig;
#pragma unroll
        for (int n = 0; n < 8; ++n) {
            uint32_t b0 = __float_as_uint(sB[(n * 8 + g) * BSTR + kc]);
            uint32_t b1 = __float_as_uint(sB[(n * 8 + g) * BSTR + kc + 4]);
            mma_tf32(c[n], tq0[ks], tq1[ks], tq2[ks], tq3[ks], b0, b1);
        }
    }

    // ---- scale + bias (fragment order, coalesced, L2-resident) --------------
    {
        const float4* bf = g_biasF + ((h * 4 + w) * 8) * 32 + lane;
#pragma unroll
        for (int n = 0; n < 8; ++n) {
            float4 bb = bf[n * 32];
            c[n][0] = fmaf(c[n][0], SCALE_L2E, bb.x);
            c[n][1] = fmaf(c[n][1], SCALE_L2E, bb.y);
            c[n][2] = fmaf(c[n][2], SCALE_L2E, bb.z);
            c[n][3] = fmaf(c[n][3], SCALE_L2E, bb.w);
        }
    }

    // ---- softmax (base-2 domain; quad holds a full row) ---------------------
    float mx0 = -1e30f, mx1 = -1e30f;
#pragma unroll
    for (int n = 0; n < 8; ++n) {
        mx0 = fmaxf(mx0, fmaxf(c[n][0], c[n][1]));
        mx1 = fmaxf(mx1, fmaxf(c[n][2], c[n][3]));
    }
#pragma unroll
    for (int d = 1; d <= 2; d <<= 1) {
        mx0 = fmaxf(mx0, __shfl_xor_sync(0xffffffffu, mx0, d));
        mx1 = fmaxf(mx1, __shfl_xor_sync(0xffffffffu, mx1, d));
    }
    float s0 = 0.f, s1 = 0.f;
#pragma unroll
    for (int n = 0; n < 8; ++n) {
        c[n][0] = exp2f(c[n][0] - mx0);
        c[n][1] = exp2f(c[n][1] - mx0);
        c[n][2] = exp2f(c[n][2] - mx1);
        c[n][3] = exp2f(c[n][3] - mx1);
        s0 += c[n][0] + c[n][1];
        s1 += c[n][2] + c[n][3];
    }
#pragma unroll
    for (int d = 1; d <= 2; d <<= 1) {
        s0 += __shfl_xor_sync(0xffffffffu, s0, d);
        s1 += __shfl_xor_sync(0xffffffffu, s1, d);
    }
    float inv0 = 1.0f / s0, inv1 = 1.0f / s1;

    // ---- all warps done with K; stage unnormalized P over sB ----------------
    __syncthreads();
#pragma unroll
    for (int n = 0; n < 8; ++n) {
        int col = n * 8 + 2 * tig;
        *(float2*)(sB + (r0 + g) * BSTR + col)     = make_float2(c[n][0], c[n][1]);
        *(float2*)(sB + (r0 + g + 8) * BSTR + col) = make_float2(c[n][2], c[n][3]);
    }
    __syncwarp();

    // ---- ensure V landed (should be long since) ------------------------------
    asm volatile("cp.async.wait_group 0;" ::: "memory");
    __syncthreads();

    // ---- O = P V : P single tf32 (rna), V raw at stride 72 -------------------
    float o[8][4];
#pragma unroll
    for (int d = 0; d < 8; ++d) {
#pragma unroll
        for (int j = 0; j < 4; ++j) o[d][j] = 0.f;
    }
#pragma unroll
    for (int ks = 0; ks < 8; ++ks) {
        const int kc = ks * 8 + tig;
        uint32_t h0 = f2tf32(sB[(r0 + g) * BSTR + kc]);
        uint32_t h1 = f2tf32(sB[(r0 + g + 8) * BSTR + kc]);
        uint32_t h2 = f2tf32(sB[(r0 + g) * BSTR + kc + 4]);
        uint32_t h3 = f2tf32(sB[(r0 + g + 8) * BSTR + kc + 4]);
#pragma unroll
        for (int dt = 0; dt < 8; ++dt) {
            uint32_t b0 = __float_as_uint(sA[(ks * 8 + tig) * VSTR + dt * 8 + g]);
            uint32_t b1 = __float_as_uint(sA[(ks * 8 + tig + 4) * VSTR + dt * 8 + g]);
            mma_tf32(o[dt], h0, h1, h2, h3, b0, b1);
        }
    }

    // ---- stage normalized O over own P rows, then coalesced rolled stores ----
    __syncwarp();
#pragma unroll
    for (int dt = 0; dt < 8; ++dt) {
        int col = dt * 8 + 2 * tig;
        *(float2*)(sB + (r0 + g) * BSTR + col)     = make_float2(o[dt][0] * inv0, o[dt][1] * inv0);
        *(float2*)(sB + (r0 + g + 8) * BSTR + col) = make_float2(o[dt][2] * inv1, o[dt][3] * inv1);
    }
    __syncthreads();

    {
        float* ob = out + (size_t)b * 32768;
        const int cbase = h * 64 - 32;
        const int c4 = tid & 15;            // 16 float4 per row
        const int col = (cbase + 4 * c4) & 511;
#pragma unroll
        for (int it = 0; it < 8; ++it) {
            int row = (tid >> 4) + 8 * it;
            float4 val = *(const float4*)(sB + row * BSTR + c4 * 4);
            *(float4*)(ob + row * 512 + col) = val;
        }
    }
}

extern "C" void kernel_launch(void* const* d_in, const int* in_sizes, int n_in,
                              void* d_out, int out_size) {
    const float* q     = (const float*)d_in[0];
    const float* k     = (const float*)d_in[1];
    const float* v     = (const float*)d_in[2];
    const float* table = (const float*)d_in[3];
    float* out = (float*)d_out;

    bias_precompute_kernel<<<32, 256>>>(table);

    const int smem_bytes = SM_FLOATS * sizeof(float);   // 35840 B
    cudaFuncSetAttribute(winattn_kernel,
                         cudaFuncAttributeMaxDynamicSharedMemorySize, smem_bytes);
    winattn_kernel<<<16384, 128, smem_bytes>>>(q, k, v, out);
}

// round 16
// speedup vs baseline: 1.4784x; 1.0500x over previous
#include <cuda_runtime.h>
#include <cstdint>

// ----------------------------------------------------------------------------
// WindowAttention: 2048 windows x 8 heads, M=N=64, D=64, fp32.
// One CTA per (b,h); 64 threads / 2 warps; each warp owns 32 query rows
// (two m16 tiles) -> every K/V B-fragment load feeds 4 HMMAs (halves the
// dominant L1 LDS traffic vs 4-warp layout).
// Q fragments pulled to REGISTERS (tf32) up-front -> V cp.async'd into the
// Q smem region at QK-mainloop START (hidden behind QK+softmax).
// sA 64x72: Q at stride 68, then V at stride 72 (both conflict-free).
// sB 64x68: K -> P -> O. 35.8 KB smem -> 6 CTAs/SM (12 warps).
// QK: Q single tf32 (rna), K raw fp32 as tf32. PV: P single tf32, V raw.
// Bias in fragment order (L2-resident). Rolled coalesced stores.
// ----------------------------------------------------------------------------

#define QSTR 68                       // mod 32 == 4 -> bank 4g+tig, conflict-free
#define BSTR 68
#define VSTR 72                       // mod 32 == 8 -> bank 8(tig+dt)+g, conflict-free
#define BOFF 4608                     // sA sized 64*72 floats
#define SM_FLOATS (4608 + 4352)       // 8960 floats = 35840 B
#define SCALE_L2E 0.1803368801111146f // 0.125 * log2(e)

__device__ float4 g_biasF[8 * 4 * 8 * 32];   // [h][blk16][n][lane], * log2e

__global__ void bias_precompute_kernel(const float* __restrict__ table) {
    int t = blockIdx.x * blockDim.x + threadIdx.x;   // 0..8191
    if (t >= 8192) return;
    int h = t >> 10, blk = (t >> 8) & 3, n = (t >> 5) & 7, lane = t & 31;
    int g = lane >> 2, tig = lane & 3;
    int rA = 16 * blk + g, rB = rA + 8;
    int col = 8 * n + 2 * tig;
    const float L2E = 1.4426950408889634f;
    float4 r;
#define BIAS_AT(rr, cc, dst) {                                   \
        int raw = ((rr) - 32) * 128 + ((cc) - 32) + 64;          \
        int idx = raw < 0 ? raw + 16129 : raw;                   \
        dst = table[(size_t)idx * 8 + h] * L2E; }
    BIAS_AT(rA, col,     r.x);
    BIAS_AT(rA, col + 1, r.y);
    BIAS_AT(rB, col,     r.z);
    BIAS_AT(rB, col + 1, r.w);
#undef BIAS_AT
    g_biasF[t] = r;
}

__device__ __forceinline__ uint32_t f2tf32(float x) {
    uint32_t r;
    asm("cvt.rna.tf32.f32 %0, %1;" : "=r"(r) : "f"(x));
    return r;
}

__device__ __forceinline__ void mma_tf32(float c[4],
                                         uint32_t a0, uint32_t a1, uint32_t a2, uint32_t a3,
                                         uint32_t b0, uint32_t b1) {
    asm volatile(
        "mma.sync.aligned.m16n8k8.row.col.f32.tf32.tf32.f32 "
        "{%0,%1,%2,%3}, {%4,%5,%6,%7}, {%8,%9}, {%0,%1,%2,%3};"
        : "+f"(c[0]), "+f"(c[1]), "+f"(c[2]), "+f"(c[3])
        : "r"(a0), "r"(a1), "r"(a2), "r"(a3), "r"(b0), "r"(b1));
}

__device__ __forceinline__ void cp16(uint32_t smem_dst, const void* gmem_src) {
    asm volatile("cp.async.cg.shared.global [%0], [%1], 16;"
                 :: "r"(smem_dst), "l"(gmem_src));
}

__global__ __launch_bounds__(64, 6) void winattn_kernel(
    const float* __restrict__ q, const float* __restrict__ k,
    const float* __restrict__ v, float* __restrict__ out) {
    extern __shared__ float smem[];
    float* sA = smem;                    // Q (stride 68), then V (stride 72)
    float* sB = smem + BOFF;             // K, then P, then O (stride 68)

    const int bh   = blockIdx.x;
    const int b    = bh >> 3;
    const int h    = bh & 7;
    const int tid  = threadIdx.x;
    const int lane = tid & 31;
    const int g    = lane >> 2;          // 0..7
    const int tig  = lane & 3;           // 0..3
    const int w    = tid >> 5;           // warp 0/1
    const int r0   = w * 32;             // warp's first query row (32 rows)

    const uint32_t sAu = (uint32_t)__cvta_generic_to_shared(sA);
    const uint32_t sBu = (uint32_t)__cvta_generic_to_shared(sB);

    // ---- async staging of raw Q (stride 68), K (stride 68) ------------------
    {
        const float4* qg = (const float4*)(q + (size_t)bh * 4096);
        const float4* kg = (const float4*)(k + (size_t)bh * 4096);
#pragma unroll
        for (int j = 0; j < 16; ++j) {
            int i = tid + 64 * j;
            int m = i >> 4, c4 = i & 15;
            cp16(sAu + (m * QSTR + c4 * 4) * 4, qg + i);
            cp16(sBu + (m * BSTR + c4 * 4) * 4, kg + i);
        }
        asm volatile("cp.async.commit_group;");
        asm volatile("cp.async.wait_group 0;" ::: "memory");
    }
    __syncthreads();

    // ---- pull ALL Q fragments (64 values, 2 tiles) to regs as tf32 ----------
    uint32_t ta0[8], ta1[8], ta2[8], ta3[8];   // tile0: rows r0+g, r0+g+8
    uint32_t tc0[8], tc1[8], tc2[8], tc3[8];   // tile1: rows r0+g+16, r0+g+24
#pragma unroll
    for (int ks = 0; ks < 8; ++ks) {
        const int kc = ks * 8 + tig;
        ta0[ks] = f2tf32(sA[(r0 + g) * QSTR + kc]);
        ta1[ks] = f2tf32(sA[(r0 + g + 8) * QSTR + kc]);
        ta2[ks] = f2tf32(sA[(r0 + g) * QSTR + kc + 4]);
        ta3[ks] = f2tf32(sA[(r0 + g + 8) * QSTR + kc + 4]);
        tc0[ks] = f2tf32(sA[(r0 + g + 16) * QSTR + kc]);
        tc1[ks] = f2tf32(sA[(r0 + g + 24) * QSTR + kc]);
        tc2[ks] = f2tf32(sA[(r0 + g + 16) * QSTR + kc + 4]);
        tc3[ks] = f2tf32(sA[(r0 + g + 24) * QSTR + kc + 4]);
    }
    __syncthreads();                     // both warps done reading Q from sA

    // ---- issue V -> sA at stride 72 NOW (hidden behind QK mainloop) ---------
    {
        const float4* vg = (const float4*)(v + (size_t)bh * 4096);
#pragma unroll
        for (int j = 0; j < 16; ++j) {
            int i = tid + 64 * j;
            int m = i >> 4, c4 = i & 15;
            cp16(sAu + (m * VSTR + c4 * 4) * 4, vg + i);
        }
        asm volatile("cp.async.commit_group;");
    }

    // ---- S = Q K^T : each B-fragment pair feeds BOTH m16 tiles --------------
    float c0[8][4], c1[8][4];
#pragma unroll
    for (int n = 0; n < 8; ++n) {
#pragma unroll
        for (int j = 0; j < 4; ++j) { c0[n][j] = 0.f; c1[n][j] = 0.f; }
    }

#pragma unroll
    for (int ks = 0; ks < 8; ++ks) {
        const int kc = ks * 8 + tig;
#pragma unroll
        for (int n = 0; n < 8; ++n) {
            uint32_t b0 = __float_as_uint(sB[(n * 8 + g) * BSTR + kc]);
            uint32_t b1 = __float_as_uint(sB[(n * 8 + g) * BSTR + kc + 4]);
            mma_tf32(c0[n], ta0[ks], ta1[ks], ta2[ks], ta3[ks], b0, b1);
            mma_tf32(c1[n], tc0[ks], tc1[ks], tc2[ks], tc3[ks], b0, b1);
        }
    }

    // ---- scale + bias (fragment order, coalesced, L2-resident) --------------
    {
        const float4* bf0 = g_biasF + ((h * 4 + 2 * w) * 8) * 32 + lane;
        const float4* bf1 = bf0 + 8 * 32;
#pragma unroll
        for (int n = 0; n < 8; ++n) {
            float4 b0 = bf0[n * 32];
            float4 b1 = bf1[n * 32];
            c0[n][0] = fmaf(c0[n][0], SCALE_L2E, b0.x);
            c0[n][1] = fmaf(c0[n][1], SCALE_L2E, b0.y);
            c0[n][2] = fmaf(c0[n][2], SCALE_L2E, b0.z);
            c0[n][3] = fmaf(c0[n][3], SCALE_L2E, b0.w);
            c1[n][0] = fmaf(c1[n][0], SCALE_L2E, b1.x);
            c1[n][1] = fmaf(c1[n][1], SCALE_L2E, b1.y);
            c1[n][2] = fmaf(c1[n][2], SCALE_L2E, b1.z);
            c1[n][3] = fmaf(c1[n][3], SCALE_L2E, b1.w);
        }
    }

    // ---- softmax (base-2 domain; quad holds a full row; 4 row-groups) -------
    float mx0 = -1e30f, mx1 = -1e30f, mx2 = -1e30f, mx3 = -1e30f;
#pragma unroll
    for (int n = 0; n < 8; ++n) {
        mx0 = fmaxf(mx0, fmaxf(c0[n][0], c0[n][1]));
        mx1 = fmaxf(mx1, fmaxf(c0[n][2], c0[n][3]));
        mx2 = fmaxf(mx2, fmaxf(c1[n][0], c1[n][1]));
        mx3 = fmaxf(mx3, fmaxf(c1[n][2], c1[n][3]));
    }
#pragma unroll
    for (int d = 1; d <= 2; d <<= 1) {
        mx0 = fmaxf(mx0, __shfl_xor_sync(0xffffffffu, mx0, d));
        mx1 = fmaxf(mx1, __shfl_xor_sync(0xffffffffu, mx1, d));
        mx2 = fmaxf(mx2, __shfl_xor_sync(0xffffffffu, mx2, d));
        mx3 = fmaxf(mx3, __shfl_xor_sync(0xffffffffu, mx3, d));
    }
    float s0 = 0.f, s1 = 0.f, s2 = 0.f, s3 = 0.f;
#pragma unroll
    for (int n = 0; n < 8; ++n) {
        c0[n][0] = exp2f(c0[n][0] - mx0);
        c0[n][1] = exp2f(c0[n][1] - mx0);
        c0[n][2] = exp2f(c0[n][2] - mx1);
        c0[n][3] = exp2f(c0[n][3] - mx1);
        c1[n][0] = exp2f(c1[n][0] - mx2);
        c1[n][1] = exp2f(c1[n][1] - mx2);
        c1[n][2] = exp2f(c1[n][2] - mx3);
        c1[n][3] = exp2f(c1[n][3] - mx3);
        s0 += c0[n][0] + c0[n][1];
        s1 += c0[n][2] + c0[n][3];
        s2 += c1[n][0] + c1[n][1];
        s3 += c1[n][2] + c1[n][3];
    }
#pragma unroll
    for (int d = 1; d <= 2; d <<= 1) {
        s0 += __shfl_xor_sync(0xffffffffu, s0, d);
        s1 += __shfl_xor_sync(0xffffffffu, s1, d);
        s2 += __shfl_xor_sync(0xffffffffu, s2, d);
        s3 += __shfl_xor_sync(0xffffffffu, s3, d);
    }
    float inv0 = 1.0f / s0, inv1 = 1.0f / s1;
    float inv2 = 1.0f / s2, inv3 = 1.0f / s3;

    // ---- all warps done with K; stage unnormalized P over sB ----------------
    __syncthreads();
#pragma unroll
    for (int n = 0; n < 8; ++n) {
        int col = n * 8 + 2 * tig;
        *(float2*)(sB + (r0 + g) * BSTR + col)      = make_float2(c0[n][0], c0[n][1]);
        *(float2*)(sB + (r0 + g + 8) * BSTR + col)  = make_float2(c0[n][2], c0[n][3]);
        *(float2*)(sB + (r0 + g + 16) * BSTR + col) = make_float2(c1[n][0], c1[n][1]);
        *(float2*)(sB + (r0 + g + 24) * BSTR + col) = make_float2(c1[n][2], c1[n][3]);
    }
    __syncwarp();

    // ---- ensure V landed (should be long since) ------------------------------
    asm volatile("cp.async.wait_group 0;" ::: "memory");
    __syncthreads();

    // ---- O = P V : P single tf32, V raw; B-fragments feed both tiles --------
    float o0[8][4], o1[8][4];
#pragma unroll
    for (int d = 0; d < 8; ++d) {
#pragma unroll
        for (int j = 0; j < 4; ++j) { o0[d][j] = 0.f; o1[d][j] = 0.f; }
    }
#pragma unroll
    for (int ks = 0; ks < 8; ++ks) {
        const int kc = ks * 8 + tig;
        uint32_t h0 = f2tf32(sB[(r0 + g) * BSTR + kc]);
        uint32_t h1 = f2tf32(sB[(r0 + g + 8) * BSTR + kc]);
        uint32_t h2 = f2tf32(sB[(r0 + g) * BSTR + kc + 4]);
        uint32_t h3 = f2tf32(sB[(r0 + g + 8) * BSTR + kc + 4]);
        uint32_t hc0 = f2tf32(sB[(r0 + g + 16) * BSTR + kc]);
        uint32_t hc1 = f2tf32(sB[(r0 + g + 24) * BSTR + kc]);
        uint32_t hc2 = f2tf32(sB[(r0 + g + 16) * BSTR + kc + 4]);
        uint32_t hc3 = f2tf32(sB[(r0 + g + 24) * BSTR + kc + 4]);
#pragma unroll
        for (int dt = 0; dt < 8; ++dt) {
            uint32_t b0 = __float_as_uint(sA[(ks * 8 + tig) * VSTR + dt * 8 + g]);
            uint32_t b1 = __float_as_uint(sA[(ks * 8 + tig + 4) * VSTR + dt * 8 + g]);
            mma_tf32(o0[dt], h0, h1, h2, h3, b0, b1);
            mma_tf32(o1[dt], hc0, hc1, hc2, hc3, b0, b1);
        }
    }

    // ---- stage normalized O over own P rows, then coalesced rolled stores ----
    __syncwarp();
#pragma unroll
    for (int dt = 0; dt < 8; ++dt) {
        int col = dt * 8 + 2 * tig;
        *(float2*)(sB + (r0 + g) * BSTR + col)      = make_float2(o0[dt][0] * inv0, o0[dt][1] * inv0);
        *(float2*)(sB + (r0 + g + 8) * BSTR + col)  = make_float2(o0[dt][2] * inv1, o0[dt][3] * inv1);
        *(float2*)(sB + (r0 + g + 16) * BSTR + col) = make_float2(o1[dt][0] * inv2, o1[dt][1] * inv2);
        *(float2*)(sB + (r0 + g + 24) * BSTR + col) = make_float2(o1[dt][2] * inv3, o1[dt][3] * inv3);
    }
    __syncthreads();

    {
        float* ob = out + (size_t)b * 32768;
        const int cbase = h * 64 - 32;
        const int c4 = tid & 15;            // 16 float4 per row
        const int col = (cbase + 4 * c4) & 511;
#pragma unroll
        for (int it = 0; it < 16; ++it) {
            int row = (tid >> 4) + 4 * it;
            float4 val = *(const float4*)(sB + row * BSTR + c4 * 4);
            *(float4*)(ob + row * 512 + col) = val;
        }
    }
}

extern "C" void kernel_launch(void* const* d_in, const int* in_sizes, int n_in,
                              void* d_out, int out_size) {
    const float* q     = (const float*)d_in[0];
    const float* k     = (const float*)d_in[1];
    const float* v     = (const float*)d_in[2];
    const float* table = (const float*)d_in[3];
    float* out = (float*)d_out;

    bias_precompute_kernel<<<32, 256>>>(table);

    const int smem_bytes = SM_FLOATS * sizeof(float);   // 35840 B
    cudaFuncSetAttribute(winattn_kernel,
                         cudaFuncAttributeMaxDynamicSharedMemorySize, smem_bytes);
    winattn_kernel<<<16384, 64, smem_bytes>>>(q, k, v, out);
}